// round 1
// baseline (speedup 1.0000x reference)
#include <cuda_runtime.h>

#define BB  2
#define TT  2048
#define DDIM 1024
#define HH  16
#define DHH 64
#define MTOT (BB*TT)   // 4096

// Scratch: Q,K,V in [B,H,T,DH] layout (16 MB each, static device globals)
__device__ float g_Q[BB*HH*TT*DHH];
__device__ float g_K[BB*HH*TT*DHH];
__device__ float g_V[BB*HH*TT*DHH];

// ---------------------------------------------------------------------------
// Kernel 1: fused QKV projection.  C = X @ W + b, output scattered to
// [B,H,T,DH].  64x64 tile, BK=16, 256 threads, 4x4 per-thread microtile.
// blockIdx.z: 0->Q(query,Wq,bq) 1->K(key,Wk,bk) 2->V(key,Wv,bv)
// ---------------------------------------------------------------------------
__global__ __launch_bounds__(256) void proj_kernel(
    const float* __restrict__ Xq, const float* __restrict__ Xk,
    const float* __restrict__ Wq, const float* __restrict__ bq,
    const float* __restrict__ Wk, const float* __restrict__ bk,
    const float* __restrict__ Wv, const float* __restrict__ bv)
{
    __shared__ __align__(16) float As[16*64];   // As[k][m]
    __shared__ __align__(16) float Bs[16*64];   // Bs[k][n]

    const int which = blockIdx.z;
    const float* X    = (which == 0) ? Xq : Xk;
    const float* W    = (which == 0) ? Wq : (which == 1) ? Wk : Wv;
    const float* bias = (which == 0) ? bq : (which == 1) ? bk : bv;
    float* out        = (which == 0) ? g_Q : (which == 1) ? g_K : g_V;

    const int tid = threadIdx.x;
    const int tx = tid & 15;       // 0..15 -> n microtile
    const int ty = tid >> 4;       // 0..15 -> m microtile
    const int m0 = blockIdx.y * 64;
    const int n0 = blockIdx.x * 64;

    // load indices
    const int a_row = tid >> 2;            // 0..63
    const int a_k   = (tid & 3) << 2;      // 0,4,8,12
    const int b_k   = tid >> 4;            // 0..15
    const int b_n   = (tid & 15) << 2;     // 0..60

    float acc[4][4] = {};

    for (int k0 = 0; k0 < DDIM; k0 += 16) {
        float4 xa = *reinterpret_cast<const float4*>(&X[(size_t)(m0 + a_row)*DDIM + k0 + a_k]);
        float4 wb = *reinterpret_cast<const float4*>(&W[(size_t)(k0 + b_k)*DDIM + n0 + b_n]);
        __syncthreads();
        As[(a_k+0)*64 + a_row] = xa.x;
        As[(a_k+1)*64 + a_row] = xa.y;
        As[(a_k+2)*64 + a_row] = xa.z;
        As[(a_k+3)*64 + a_row] = xa.w;
        *reinterpret_cast<float4*>(&Bs[b_k*64 + b_n]) = wb;
        __syncthreads();

        #pragma unroll
        for (int k = 0; k < 16; k++) {
            float a0 = As[k*64 + ty*4 + 0];
            float a1 = As[k*64 + ty*4 + 1];
            float a2 = As[k*64 + ty*4 + 2];
            float a3 = As[k*64 + ty*4 + 3];
            float4 b4 = *reinterpret_cast<const float4*>(&Bs[k*64 + tx*4]);
            acc[0][0] += a0*b4.x; acc[0][1] += a0*b4.y; acc[0][2] += a0*b4.z; acc[0][3] += a0*b4.w;
            acc[1][0] += a1*b4.x; acc[1][1] += a1*b4.y; acc[1][2] += a1*b4.z; acc[1][3] += a1*b4.w;
            acc[2][0] += a2*b4.x; acc[2][1] += a2*b4.y; acc[2][2] += a2*b4.z; acc[2][3] += a2*b4.w;
            acc[3][0] += a3*b4.x; acc[3][1] += a3*b4.y; acc[3][2] += a3*b4.z; acc[3][3] += a3*b4.w;
        }
    }

    // epilogue: add bias, scatter to [B,H,T,DH]
    #pragma unroll
    for (int i = 0; i < 4; i++) {
        int m  = m0 + ty*4 + i;
        int bb = m >> 11;          // / TT
        int t  = m & (TT-1);
        #pragma unroll
        for (int j = 0; j < 4; j++) {
            int n  = n0 + tx*4 + j;
            int h  = n >> 6;
            int dh = n & 63;
            out[(((size_t)(bb*HH + h)*TT) + t)*DHH + dh] = acc[i][j] + bias[n];
        }
    }
}

// ---------------------------------------------------------------------------
// Kernel 2: flash attention, fp32.  BQ=BK=64, 256 threads, one (b,h,qtile)
// per CTA.  Smem: Qs + K/P shared buffer + Vs = 48 KB exactly.
// Shift-swizzle (d+row)&63 on Qs/Ks/Ps to avoid bank conflicts.
// ---------------------------------------------------------------------------
__global__ __launch_bounds__(256) void attn_kernel(
    const float* __restrict__ amask, const int* __restrict__ mfp,
    float* __restrict__ out)
{
    __shared__ __align__(16) float Qs [64*64];
    __shared__ __align__(16) float KPs[64*64];  // K tile, then reused for P
    __shared__ __align__(16) float Vs [64*64];

    const int tid = threadIdx.x;
    const int tx = tid & 15;
    const int ty = tid >> 4;
    const int b  = blockIdx.z;
    const int h  = blockIdx.y;
    const int q0 = blockIdx.x * 64;
    const int mf = __ldg(mfp);

    const size_t head_off = (size_t)(b*HH + h) * TT * DHH;
    const float* Qp = g_Q + head_off;
    const float* Kp = g_K + head_off;
    const float* Vp = g_V + head_off;

    // load Q tile (swizzled)
    for (int l = tid; l < 1024; l += 256) {
        int r  = l >> 4;
        int d0 = (l & 15) << 2;
        float4 v = *reinterpret_cast<const float4*>(&Qp[(size_t)(q0 + r)*DHH + d0]);
        Qs[r*64 + ((d0+0 + r) & 63)] = v.x;
        Qs[r*64 + ((d0+1 + r) & 63)] = v.y;
        Qs[r*64 + ((d0+2 + r) & 63)] = v.z;
        Qs[r*64 + ((d0+3 + r) & 63)] = v.w;
    }

    int r_[4], c_[4];
    #pragma unroll
    for (int i = 0; i < 4; i++) { r_[i] = ty*4 + i; c_[i] = tx*4 + i; }

    float o[4][4] = {};
    float mrow[4], lrow[4];
    #pragma unroll
    for (int i = 0; i < 4; i++) { mrow[i] = -1e30f; lrow[i] = 0.0f; }

    for (int kt = 0; kt < TT/64; kt++) {
        const int k0 = kt * 64;

        __syncthreads();   // previous iteration done with KPs/Vs; Q stores visible
        for (int l = tid; l < 1024; l += 256) {
            int r  = l >> 4;
            int d0 = (l & 15) << 2;
            float4 kv = *reinterpret_cast<const float4*>(&Kp[(size_t)(k0 + r)*DHH + d0]);
            KPs[r*64 + ((d0+0 + r) & 63)] = kv.x;
            KPs[r*64 + ((d0+1 + r) & 63)] = kv.y;
            KPs[r*64 + ((d0+2 + r) & 63)] = kv.z;
            KPs[r*64 + ((d0+3 + r) & 63)] = kv.w;
            float4 vv = *reinterpret_cast<const float4*>(&Vp[(size_t)(k0 + r)*DHH + d0]);
            *reinterpret_cast<float4*>(&Vs[r*64 + d0]) = vv;
        }
        __syncthreads();

        // S = Q K^T  (4x4 per thread)
        float s[4][4] = {};
        #pragma unroll 16
        for (int d = 0; d < 64; d++) {
            float a0 = Qs [r_[0]*64 + ((d + r_[0]) & 63)];
            float a1 = Qs [r_[1]*64 + ((d + r_[1]) & 63)];
            float a2 = Qs [r_[2]*64 + ((d + r_[2]) & 63)];
            float a3 = Qs [r_[3]*64 + ((d + r_[3]) & 63)];
            float k0v = KPs[c_[0]*64 + ((d + c_[0]) & 63)];
            float k1v = KPs[c_[1]*64 + ((d + c_[1]) & 63)];
            float k2v = KPs[c_[2]*64 + ((d + c_[2]) & 63)];
            float k3v = KPs[c_[3]*64 + ((d + c_[3]) & 63)];
            s[0][0] += a0*k0v; s[0][1] += a0*k1v; s[0][2] += a0*k2v; s[0][3] += a0*k3v;
            s[1][0] += a1*k0v; s[1][1] += a1*k1v; s[1][2] += a1*k2v; s[1][3] += a1*k3v;
            s[2][0] += a2*k0v; s[2][1] += a2*k1v; s[2][2] += a2*k2v; s[2][3] += a2*k3v;
            s[3][0] += a3*k0v; s[3][1] += a3*k1v; s[3][2] += a3*k2v; s[3][3] += a3*k3v;
        }

        // scale + additive mask + optional causal
        float mcol[4];
        #pragma unroll
        for (int j = 0; j < 4; j++) mcol[j] = __ldg(&amask[(size_t)b*TT + k0 + c_[j]]);
        #pragma unroll
        for (int i = 0; i < 4; i++) {
            #pragma unroll
            for (int j = 0; j < 4; j++) {
                float v = s[i][j]*0.125f + mcol[j];
                if (mf && (k0 + c_[j] >= q0 + r_[i])) v = -1e30f;
                s[i][j] = v;
            }
        }

        // online softmax per row
        #pragma unroll
        for (int i = 0; i < 4; i++) {
            float rm = fmaxf(fmaxf(s[i][0], s[i][1]), fmaxf(s[i][2], s[i][3]));
            #pragma unroll
            for (int off = 8; off >= 1; off >>= 1)
                rm = fmaxf(rm, __shfl_xor_sync(0xffffffffu, rm, off));
            float mnew  = fmaxf(mrow[i], rm);
            float alpha = __expf(mrow[i] - mnew);
            float rs = 0.0f;
            #pragma unroll
            for (int j = 0; j < 4; j++) {
                s[i][j] = __expf(s[i][j] - mnew);
                rs += s[i][j];
            }
            #pragma unroll
            for (int off = 8; off >= 1; off >>= 1)
                rs += __shfl_xor_sync(0xffffffffu, rs, off);
            lrow[i] = lrow[i]*alpha + rs;
            mrow[i] = mnew;
            #pragma unroll
            for (int j = 0; j < 4; j++) o[i][j] *= alpha;
        }

        __syncthreads();   // everyone done reading K from KPs
        #pragma unroll
        for (int i = 0; i < 4; i++)
            #pragma unroll
            for (int j = 0; j < 4; j++)
                KPs[r_[i]*64 + ((c_[j] + r_[i]) & 63)] = s[i][j];
        __syncthreads();

        // O += P V   (4 rows x 4 dh-cols per thread)
        #pragma unroll 8
        for (int c = 0; c < 64; c++) {
            float4 v4 = *reinterpret_cast<const float4*>(&Vs[c*64 + tx*4]);
            float p0 = KPs[r_[0]*64 + ((c + r_[0]) & 63)];
            float p1 = KPs[r_[1]*64 + ((c + r_[1]) & 63)];
            float p2 = KPs[r_[2]*64 + ((c + r_[2]) & 63)];
            float p3 = KPs[r_[3]*64 + ((c + r_[3]) & 63)];
            o[0][0] += p0*v4.x; o[0][1] += p0*v4.y; o[0][2] += p0*v4.z; o[0][3] += p0*v4.w;
            o[1][0] += p1*v4.x; o[1][1] += p1*v4.y; o[1][2] += p1*v4.z; o[1][3] += p1*v4.w;
            o[2][0] += p2*v4.x; o[2][1] += p2*v4.y; o[2][2] += p2*v4.z; o[2][3] += p2*v4.w;
            o[3][0] += p3*v4.x; o[3][1] += p3*v4.y; o[3][2] += p3*v4.z; o[3][3] += p3*v4.w;
        }
    }

    // epilogue: normalize and write [B,T,D] with D col = h*64 + dh
    #pragma unroll
    for (int i = 0; i < 4; i++) {
        float inv_l = 1.0f / lrow[i];
        size_t row_off = ((size_t)b*TT + q0 + r_[i]) * DDIM + h*64;
        #pragma unroll
        for (int j = 0; j < 4; j++)
            out[row_off + c_[j]] = o[i][j] * inv_l;
    }
}

// ---------------------------------------------------------------------------
extern "C" void kernel_launch(void* const* d_in, const int* in_sizes, int n_in,
                              void* d_out, int out_size)
{
    const float* q     = (const float*)d_in[0];
    const float* k     = (const float*)d_in[1];
    const float* amask = (const float*)d_in[2];
    const float* Wq    = (const float*)d_in[3];
    const float* bq    = (const float*)d_in[4];
    const float* Wk    = (const float*)d_in[5];
    const float* bk    = (const float*)d_in[6];
    const float* Wv    = (const float*)d_in[7];
    const float* bv    = (const float*)d_in[8];
    const int*   mf    = (const int*)  d_in[9];
    float* out = (float*)d_out;

    dim3 gp(DDIM/64, MTOT/64, 3);     // (16, 64, 3)
    proj_kernel<<<gp, 256>>>(q, k, Wq, bq, Wk, bk, Wv, bv);

    dim3 ga(TT/64, HH, BB);           // (32, 16, 2)
    attn_kernel<<<ga, 256>>>(amask, mf, out);
}

// round 2
// speedup vs baseline: 4.2631x; 4.2631x over previous
#include <cuda_runtime.h>

#define BB  2
#define TT  2048
#define DDIM 1024
#define HH  16
#define DHH 64
#define MTOT (BB*TT)   // 4096

// Scratch: Q,K,V in [B,H,T,DH] layout, values pre-rounded to tf32 (fp32 bits)
__device__ float g_Q[BB*HH*TT*DHH];
__device__ float g_K[BB*HH*TT*DHH];
__device__ float g_V[BB*HH*TT*DHH];

__device__ __forceinline__ unsigned f2tf(float f) {
    unsigned u;
    asm("cvt.rna.tf32.f32 %0, %1;" : "=r"(u) : "f"(f));
    return u;
}

__device__ __forceinline__ void mma_tf32(float c[4],
    unsigned a0, unsigned a1, unsigned a2, unsigned a3,
    unsigned b0, unsigned b1)
{
    asm volatile(
        "mma.sync.aligned.m16n8k8.row.col.f32.tf32.tf32.f32 "
        "{%0,%1,%2,%3}, {%4,%5,%6,%7}, {%8,%9}, {%0,%1,%2,%3};"
        : "+f"(c[0]), "+f"(c[1]), "+f"(c[2]), "+f"(c[3])
        : "r"(a0), "r"(a1), "r"(a2), "r"(a3), "r"(b0), "r"(b1));
}

// ---------------------------------------------------------------------------
// Kernel 1: fused QKV projection, tf32 tensor cores.
// C = X @ W + b.  BM=128, BN=128, BK=32, 256 threads (8 warps, 4x2).
// Warp tile 32x64 (2 m-frags x 8 n-frags).  Output scattered to [B,H,T,DH],
// tf32-rounded so the attention kernel can consume raw bits.
// ---------------------------------------------------------------------------
#define AS_STRIDE 36    // 36 % 32 == 4 -> A-frag access conflict-free
#define BS_STRIDE 136   // 136 % 32 == 8 -> B-frag access conflict-free

__global__ __launch_bounds__(256) void proj_kernel(
    const float* __restrict__ Xq, const float* __restrict__ Xk,
    const float* __restrict__ Wq, const float* __restrict__ bq,
    const float* __restrict__ Wk, const float* __restrict__ bk,
    const float* __restrict__ Wv, const float* __restrict__ bv)
{
    __shared__ __align__(16) unsigned As[128*AS_STRIDE];  // [m][k] tf32
    __shared__ __align__(16) unsigned Bs[32*BS_STRIDE];   // [k][n] tf32

    const int which = blockIdx.z;
    const float* X    = (which == 0) ? Xq : Xk;
    const float* W    = (which == 0) ? Wq : (which == 1) ? Wk : Wv;
    const float* bias = (which == 0) ? bq : (which == 1) ? bk : bv;
    float* out        = (which == 0) ? g_Q : (which == 1) ? g_K : g_V;

    const int tid  = threadIdx.x;
    const int lane = tid & 31;
    const int warp = tid >> 5;
    const int g    = lane >> 2;     // groupID 0..7
    const int tig  = lane & 3;      // thread-in-group 0..3
    const int wm   = warp & 3;      // 0..3 -> m offset wm*32
    const int wn   = warp >> 2;     // 0..1 -> n offset wn*64
    const int m0   = blockIdx.y * 128;
    const int n0   = blockIdx.x * 128;

    float acc[2][8][4] = {};

    for (int k0 = 0; k0 < DDIM; k0 += 32) {
        __syncthreads();
        // X tile 128x32 -> As
        #pragma unroll
        for (int i = 0; i < 4; i++) {
            int row = (tid >> 3) + i*32;
            int c   = (tid & 7) << 2;
            float4 v = *reinterpret_cast<const float4*>(&X[(size_t)(m0 + row)*DDIM + k0 + c]);
            uint4 u = { f2tf(v.x), f2tf(v.y), f2tf(v.z), f2tf(v.w) };
            *reinterpret_cast<uint4*>(&As[row*AS_STRIDE + c]) = u;
        }
        // W tile 32x128 -> Bs
        #pragma unroll
        for (int i = 0; i < 4; i++) {
            int kk = (tid >> 5) + i*8;
            int c  = lane << 2;
            float4 v = *reinterpret_cast<const float4*>(&W[(size_t)(k0 + kk)*DDIM + n0 + c]);
            uint4 u = { f2tf(v.x), f2tf(v.y), f2tf(v.z), f2tf(v.w) };
            *reinterpret_cast<uint4*>(&Bs[kk*BS_STRIDE + c]) = u;
        }
        __syncthreads();

        #pragma unroll
        for (int ks = 0; ks < 4; ks++) {
            unsigned a[2][4];
            #pragma unroll
            for (int mf = 0; mf < 2; mf++) {
                int r = wm*32 + mf*16 + g;
                int c = ks*8 + tig;
                a[mf][0] = As[(r    )*AS_STRIDE + c    ];
                a[mf][1] = As[(r + 8)*AS_STRIDE + c    ];
                a[mf][2] = As[(r    )*AS_STRIDE + c + 4];
                a[mf][3] = As[(r + 8)*AS_STRIDE + c + 4];
            }
            #pragma unroll
            for (int nf = 0; nf < 8; nf++) {
                int n = wn*64 + nf*8 + g;
                unsigned b0 = Bs[(ks*8 + tig    )*BS_STRIDE + n];
                unsigned b1 = Bs[(ks*8 + tig + 4)*BS_STRIDE + n];
                mma_tf32(acc[0][nf], a[0][0], a[0][1], a[0][2], a[0][3], b0, b1);
                mma_tf32(acc[1][nf], a[1][0], a[1][1], a[1][2], a[1][3], b0, b1);
            }
        }
    }

    // epilogue: add bias, round to tf32, scatter to [B,H,T,DH]
    #pragma unroll
    for (int mf = 0; mf < 2; mf++) {
        #pragma unroll
        for (int nf = 0; nf < 8; nf++) {
            int col = n0 + wn*64 + nf*8 + tig*2;
            int h   = col >> 6;
            int dh  = col & 63;
            float bz0 = bias[col], bz1 = bias[col+1];
            #pragma unroll
            for (int half = 0; half < 2; half++) {
                int row = m0 + wm*32 + mf*16 + g + half*8;
                int bb  = row >> 11;
                int t   = row & (TT-1);
                float2 v;
                v.x = __uint_as_float(f2tf(acc[mf][nf][half*2 + 0] + bz0));
                v.y = __uint_as_float(f2tf(acc[mf][nf][half*2 + 1] + bz1));
                *reinterpret_cast<float2*>(
                    &out[(((size_t)(bb*HH + h)*TT) + t)*DHH + dh]) = v;
            }
        }
    }
}

// ---------------------------------------------------------------------------
// Kernel 2: flash attention, tf32 tensor cores.  BQ=BK=64, 128 threads
// (4 warps, warp = 16 q-rows).  Q held in registers as A-fragments.
// KPs buffer (stride 68) holds K tile, then reused for P tile.
// Vs (stride 72): conflict-free B-frag access.
// ---------------------------------------------------------------------------
#define KP_STRIDE 68   // 68 % 32 == 4
#define V_STRIDE  72   // 72 % 32 == 8

__global__ __launch_bounds__(128) void attn_kernel(
    const float* __restrict__ amask, const int* __restrict__ mfp,
    float* __restrict__ out)
{
    __shared__ __align__(16) unsigned KPs[64*KP_STRIDE];
    __shared__ __align__(16) unsigned Vs [64*V_STRIDE];
    __shared__ float msk_s[64];

    const int tid  = threadIdx.x;
    const int lane = tid & 31;
    const int w    = tid >> 5;     // warp 0..3
    const int g    = lane >> 2;
    const int tig  = lane & 3;
    const int b    = blockIdx.z;
    const int h    = blockIdx.y;
    const int q0   = blockIdx.x * 64;
    const int mf   = __ldg(mfp);

    const size_t head_off = (size_t)(b*HH + h) * TT * DHH;
    const float* Qp = g_Q + head_off;
    const unsigned* Kp = reinterpret_cast<const unsigned*>(g_K) + head_off;
    const unsigned* Vp = reinterpret_cast<const unsigned*>(g_V) + head_off;

    // Q A-fragments in registers (values already tf32-rounded by proj)
    unsigned qa[8][4];
    {
        const int r0 = q0 + w*16 + g;
        const int r1 = r0 + 8;
        #pragma unroll
        for (int ks = 0; ks < 8; ks++) {
            int c = ks*8 + tig;
            qa[ks][0] = __float_as_uint(Qp[(size_t)r0*DHH + c    ]);
            qa[ks][1] = __float_as_uint(Qp[(size_t)r1*DHH + c    ]);
            qa[ks][2] = __float_as_uint(Qp[(size_t)r0*DHH + c + 4]);
            qa[ks][3] = __float_as_uint(Qp[(size_t)r1*DHH + c + 4]);
        }
    }

    float o[8][4] = {};
    float m0r = -1e30f, m1r = -1e30f, l0 = 0.0f, l1 = 0.0f;
    const int row0g = q0 + w*16 + g;   // global q row for softmax halves
    const int row1g = row0g + 8;

    for (int kt = 0; kt < TT/64; kt++) {
        const int k0 = kt * 64;

        __syncthreads();   // done with previous P (KPs) and V tiles
        for (int l = tid; l < 1024; l += 128) {
            int r = l >> 4;
            int c = (l & 15) << 2;
            uint4 kv = *reinterpret_cast<const uint4*>(&Kp[(size_t)(k0 + r)*DHH + c]);
            *reinterpret_cast<uint4*>(&KPs[r*KP_STRIDE + c]) = kv;
            uint4 vv = *reinterpret_cast<const uint4*>(&Vp[(size_t)(k0 + r)*DHH + c]);
            *reinterpret_cast<uint4*>(&Vs[r*V_STRIDE + c]) = vv;
        }
        if (tid < 16)
            *reinterpret_cast<float4*>(&msk_s[tid*4]) =
                *reinterpret_cast<const float4*>(&amask[(size_t)b*TT + k0 + tid*4]);
        __syncthreads();

        // S = Q K^T
        float s[8][4] = {};
        #pragma unroll
        for (int ks = 0; ks < 8; ks++) {
            #pragma unroll
            for (int nf = 0; nf < 8; nf++) {
                unsigned b0 = KPs[(nf*8 + g)*KP_STRIDE + ks*8 + tig    ];
                unsigned b1 = KPs[(nf*8 + g)*KP_STRIDE + ks*8 + tig + 4];
                mma_tf32(s[nf], qa[ks][0], qa[ks][1], qa[ks][2], qa[ks][3], b0, b1);
            }
        }

        // scale + additive mask + optional causal
        #pragma unroll
        for (int nf = 0; nf < 8; nf++) {
            int cl = nf*8 + tig*2;
            float mk0 = msk_s[cl], mk1 = msk_s[cl+1];
            s[nf][0] = s[nf][0]*0.125f + mk0;
            s[nf][1] = s[nf][1]*0.125f + mk1;
            s[nf][2] = s[nf][2]*0.125f + mk0;
            s[nf][3] = s[nf][3]*0.125f + mk1;
            if (mf) {
                int c0g = k0 + cl, c1g = c0g + 1;
                if (c0g >= row0g) s[nf][0] = -1e30f;
                if (c1g >= row0g) s[nf][1] = -1e30f;
                if (c0g >= row1g) s[nf][2] = -1e30f;
                if (c1g >= row1g) s[nf][3] = -1e30f;
            }
        }

        // online softmax (two rows per thread)
        float rm0 = -1e30f, rm1 = -1e30f;
        #pragma unroll
        for (int nf = 0; nf < 8; nf++) {
            rm0 = fmaxf(rm0, fmaxf(s[nf][0], s[nf][1]));
            rm1 = fmaxf(rm1, fmaxf(s[nf][2], s[nf][3]));
        }
        rm0 = fmaxf(rm0, __shfl_xor_sync(0xffffffffu, rm0, 1));
        rm0 = fmaxf(rm0, __shfl_xor_sync(0xffffffffu, rm0, 2));
        rm1 = fmaxf(rm1, __shfl_xor_sync(0xffffffffu, rm1, 1));
        rm1 = fmaxf(rm1, __shfl_xor_sync(0xffffffffu, rm1, 2));

        float mn0 = fmaxf(m0r, rm0);
        float mn1 = fmaxf(m1r, rm1);
        float al0 = __expf(m0r - mn0);
        float al1 = __expf(m1r - mn1);
        m0r = mn0; m1r = mn1;

        float rs0 = 0.0f, rs1 = 0.0f;
        #pragma unroll
        for (int nf = 0; nf < 8; nf++) {
            s[nf][0] = __expf(s[nf][0] - mn0);
            s[nf][1] = __expf(s[nf][1] - mn0);
            s[nf][2] = __expf(s[nf][2] - mn1);
            s[nf][3] = __expf(s[nf][3] - mn1);
            rs0 += s[nf][0] + s[nf][1];
            rs1 += s[nf][2] + s[nf][3];
        }
        rs0 += __shfl_xor_sync(0xffffffffu, rs0, 1);
        rs0 += __shfl_xor_sync(0xffffffffu, rs0, 2);
        rs1 += __shfl_xor_sync(0xffffffffu, rs1, 1);
        rs1 += __shfl_xor_sync(0xffffffffu, rs1, 2);
        l0 = l0*al0 + rs0;
        l1 = l1*al1 + rs1;

        #pragma unroll
        for (int nf = 0; nf < 8; nf++) {
            o[nf][0] *= al0; o[nf][1] *= al0;
            o[nf][2] *= al1; o[nf][3] *= al1;
        }

        __syncthreads();   // all warps done reading K from KPs
        // store P (tf32-rounded) into KPs
        {
            int r0 = w*16 + g, r1 = r0 + 8;
            #pragma unroll
            for (int nf = 0; nf < 8; nf++) {
                int c = nf*8 + tig*2;
                KPs[r0*KP_STRIDE + c    ] = f2tf(s[nf][0]);
                KPs[r0*KP_STRIDE + c + 1] = f2tf(s[nf][1]);
                KPs[r1*KP_STRIDE + c    ] = f2tf(s[nf][2]);
                KPs[r1*KP_STRIDE + c + 1] = f2tf(s[nf][3]);
            }
        }
        __syncthreads();

        // O += P V
        #pragma unroll
        for (int ks = 0; ks < 8; ks++) {
            int r0 = w*16 + g;
            int c  = ks*8 + tig;
            unsigned pa0 = KPs[(r0    )*KP_STRIDE + c    ];
            unsigned pa1 = KPs[(r0 + 8)*KP_STRIDE + c    ];
            unsigned pa2 = KPs[(r0    )*KP_STRIDE + c + 4];
            unsigned pa3 = KPs[(r0 + 8)*KP_STRIDE + c + 4];
            #pragma unroll
            for (int nf = 0; nf < 8; nf++) {
                unsigned b0 = Vs[(ks*8 + tig    )*V_STRIDE + nf*8 + g];
                unsigned b1 = Vs[(ks*8 + tig + 4)*V_STRIDE + nf*8 + g];
                mma_tf32(o[nf], pa0, pa1, pa2, pa3, b0, b1);
            }
        }
    }

    // epilogue: normalize and write [B,T,D]
    float inv0 = 1.0f / l0;
    float inv1 = 1.0f / l1;
    #pragma unroll
    for (int nf = 0; nf < 8; nf++) {
        int col = h*64 + nf*8 + tig*2;
        float2 v0 = { o[nf][0]*inv0, o[nf][1]*inv0 };
        float2 v1 = { o[nf][2]*inv1, o[nf][3]*inv1 };
        *reinterpret_cast<float2*>(&out[((size_t)b*TT + row0g)*DDIM + col]) = v0;
        *reinterpret_cast<float2*>(&out[((size_t)b*TT + row1g)*DDIM + col]) = v1;
    }
}

// ---------------------------------------------------------------------------
extern "C" void kernel_launch(void* const* d_in, const int* in_sizes, int n_in,
                              void* d_out, int out_size)
{
    const float* q     = (const float*)d_in[0];
    const float* k     = (const float*)d_in[1];
    const float* amask = (const float*)d_in[2];
    const float* Wq    = (const float*)d_in[3];
    const float* bq    = (const float*)d_in[4];
    const float* Wk    = (const float*)d_in[5];
    const float* bk    = (const float*)d_in[6];
    const float* Wv    = (const float*)d_in[7];
    const float* bv    = (const float*)d_in[8];
    const int*   mf    = (const int*)  d_in[9];
    float* out = (float*)d_out;

    dim3 gp(DDIM/128, MTOT/128, 3);   // (8, 32, 3)
    proj_kernel<<<gp, 256>>>(q, k, Wq, bq, Wk, bk, Wv, bv);

    dim3 ga(TT/64, HH, BB);           // (32, 16, 2)
    attn_kernel<<<ga, 128>>>(amask, mf, out);
}

// round 3
// speedup vs baseline: 4.5086x; 1.0576x over previous
#include <cuda_runtime.h>

#define BB  2
#define TT  2048
#define DDIM 1024
#define HH  16
#define DHH 64
#define MTOT (BB*TT)   // 4096

// Scratch: Q,K,V in [B,H,T,DH] layout, values pre-rounded to tf32 (fp32 bits)
__device__ float g_Q[BB*HH*TT*DHH];
__device__ float g_K[BB*HH*TT*DHH];
__device__ float g_V[BB*HH*TT*DHH];

__device__ __forceinline__ unsigned f2tf(float f) {
    unsigned u;
    asm("cvt.rna.tf32.f32 %0, %1;" : "=r"(u) : "f"(f));
    return u;
}

__device__ __forceinline__ void mma_tf32(float c[4],
    unsigned a0, unsigned a1, unsigned a2, unsigned a3,
    unsigned b0, unsigned b1)
{
    asm volatile(
        "mma.sync.aligned.m16n8k8.row.col.f32.tf32.tf32.f32 "
        "{%0,%1,%2,%3}, {%4,%5,%6,%7}, {%8,%9}, {%0,%1,%2,%3};"
        : "+f"(c[0]), "+f"(c[1]), "+f"(c[2]), "+f"(c[3])
        : "r"(a0), "r"(a1), "r"(a2), "r"(a3), "r"(b0), "r"(b1));
}

__device__ __forceinline__ void cpa16(void* smem_dst, const void* gmem_src) {
    unsigned s = (unsigned)__cvta_generic_to_shared(smem_dst);
    asm volatile("cp.async.cg.shared.global [%0], [%1], 16;\n" :: "r"(s), "l"(gmem_src));
}
__device__ __forceinline__ void cp_commit() { asm volatile("cp.async.commit_group;\n" ::); }
__device__ __forceinline__ void cp_wait1() { asm volatile("cp.async.wait_group 1;\n" ::); }
__device__ __forceinline__ void cp_wait0() { asm volatile("cp.async.wait_group 0;\n" ::); }

// ---------------------------------------------------------------------------
// Kernel 1: fused QKV projection, tf32 tensor cores, cp.async double-buffered.
// BM=128, BN=128, BK=32, 256 threads (8 warps, 4x2).  Raw fp32 staged in smem,
// tf32 conversion at fragment read.  Output tf32-rounded, scattered [B,H,T,DH].
// ---------------------------------------------------------------------------
#define PAS 36     // A stride: 36 % 32 == 4 -> conflict-free A-frag reads
#define PBS 136    // B stride: 136 % 32 == 8 -> conflict-free B-frag reads
#define P_STAGE (128*PAS + 32*PBS)          // 8960 words per stage
#define P_SMEM_BYTES (2*P_STAGE*4)          // 71680 B

__global__ __launch_bounds__(256) void proj_kernel(
    const float* __restrict__ Xq, const float* __restrict__ Xk,
    const float* __restrict__ Wq, const float* __restrict__ bq,
    const float* __restrict__ Wk, const float* __restrict__ bk,
    const float* __restrict__ Wv, const float* __restrict__ bv)
{
    extern __shared__ float psm[];

    const int which = blockIdx.z;
    const float* X    = (which == 0) ? Xq : Xk;
    const float* W    = (which == 0) ? Wq : (which == 1) ? Wk : Wv;
    const float* bias = (which == 0) ? bq : (which == 1) ? bk : bv;
    float* out        = (which == 0) ? g_Q : (which == 1) ? g_K : g_V;

    const int tid  = threadIdx.x;
    const int lane = tid & 31;
    const int warp = tid >> 5;
    const int g    = lane >> 2;
    const int tig  = lane & 3;
    const int wm   = warp & 3;
    const int wn   = warp >> 2;
    const int m0   = blockIdx.y * 128;
    const int n0   = blockIdx.x * 128;

    auto prefetch = [&](int k0, int st) {
        float* As = psm + st * P_STAGE;
        float* Bs = As + 128*PAS;
        #pragma unroll
        for (int i = 0; i < 4; i++) {
            int idx = tid + i*256;
            int r = idx >> 3, c = (idx & 7) << 2;
            cpa16(&As[r*PAS + c], &X[(size_t)(m0 + r)*DDIM + k0 + c]);
        }
        #pragma unroll
        for (int i = 0; i < 4; i++) {
            int idx = tid + i*256;
            int r = idx >> 5, c = (idx & 31) << 2;
            cpa16(&Bs[r*PBS + c], &W[(size_t)(k0 + r)*DDIM + n0 + c]);
        }
    };

    float acc[2][8][4] = {};

    prefetch(0, 0);
    cp_commit();

    for (int kt = 0; kt < DDIM/32; kt++) {
        if (kt + 1 < DDIM/32) {
            prefetch((kt+1)*32, (kt+1) & 1);
            cp_commit();
            cp_wait1();
        } else {
            cp_wait0();
        }
        __syncthreads();

        const float* As = psm + (kt & 1) * P_STAGE;
        const float* Bs = As + 128*PAS;

        #pragma unroll
        for (int ks = 0; ks < 4; ks++) {
            unsigned a[2][4];
            #pragma unroll
            for (int mfm = 0; mfm < 2; mfm++) {
                int r = wm*32 + mfm*16 + g;
                int c = ks*8 + tig;
                a[mfm][0] = f2tf(As[(r    )*PAS + c    ]);
                a[mfm][1] = f2tf(As[(r + 8)*PAS + c    ]);
                a[mfm][2] = f2tf(As[(r    )*PAS + c + 4]);
                a[mfm][3] = f2tf(As[(r + 8)*PAS + c + 4]);
            }
            #pragma unroll
            for (int nf = 0; nf < 8; nf++) {
                int n = wn*64 + nf*8 + g;
                unsigned b0 = f2tf(Bs[(ks*8 + tig    )*PBS + n]);
                unsigned b1 = f2tf(Bs[(ks*8 + tig + 4)*PBS + n]);
                mma_tf32(acc[0][nf], a[0][0], a[0][1], a[0][2], a[0][3], b0, b1);
                mma_tf32(acc[1][nf], a[1][0], a[1][1], a[1][2], a[1][3], b0, b1);
            }
        }
        __syncthreads();
    }

    // epilogue: add bias, round to tf32, scatter to [B,H,T,DH]
    #pragma unroll
    for (int mfm = 0; mfm < 2; mfm++) {
        #pragma unroll
        for (int nf = 0; nf < 8; nf++) {
            int col = n0 + wn*64 + nf*8 + tig*2;
            int h   = col >> 6;
            int dh  = col & 63;
            float bz0 = bias[col], bz1 = bias[col+1];
            #pragma unroll
            for (int half = 0; half < 2; half++) {
                int row = m0 + wm*32 + mfm*16 + g + half*8;
                int bb  = row >> 11;
                int t   = row & (TT-1);
                float2 v;
                v.x = __uint_as_float(f2tf(acc[mfm][nf][half*2 + 0] + bz0));
                v.y = __uint_as_float(f2tf(acc[mfm][nf][half*2 + 1] + bz1));
                *reinterpret_cast<float2*>(
                    &out[(((size_t)(bb*HH + h)*TT) + t)*DHH + dh]) = v;
            }
        }
    }
}

// ---------------------------------------------------------------------------
// Kernel 2: flash attention, tf32 tensor cores.
// BQ=128 (4 warps, warp m=32), BK=64, Q in registers, K/V/mask cp.async
// double-buffered.  P converted S-frag -> A-frag via warp shuffles (no smem
// round trip, no extra barriers).
// ---------------------------------------------------------------------------
#define KSTRIDE 68                      // 68 % 32 == 4
#define VSTRIDE 72                      // 72 % 32 == 8
#define MSK_OFF (64*KSTRIDE)            // 4352 words
#define A_KSTAGE (MSK_OFF + 64)         // 4416 words (K tile + mask)
#define A_STAGE  (A_KSTAGE + 64*VSTRIDE)// 9024 words per stage
#define A_SMEM_BYTES (2*A_STAGE*4)      // 72192 B

__global__ __launch_bounds__(128) void attn_kernel(
    const float* __restrict__ amask, const int* __restrict__ mfp,
    float* __restrict__ out)
{
    extern __shared__ unsigned smem[];

    const int tid  = threadIdx.x;
    const int lane = tid & 31;
    const int w    = tid >> 5;
    const int g    = lane >> 2;
    const int tig  = lane & 3;
    const int b    = blockIdx.z;
    const int h    = blockIdx.y;
    const int q0   = blockIdx.x * 128;
    const int mf   = __ldg(mfp);

    const size_t head_off = (size_t)(b*HH + h) * TT * DHH;
    const unsigned* Qp = reinterpret_cast<const unsigned*>(g_Q) + head_off;
    const unsigned* Kp = reinterpret_cast<const unsigned*>(g_K) + head_off;
    const unsigned* Vp = reinterpret_cast<const unsigned*>(g_V) + head_off;
    const float* mrow  = amask + (size_t)b*TT;

    // Q A-fragments in registers (bits already tf32-rounded by proj)
    unsigned qa[2][8][4];
    {
        const int rb = q0 + w*32 + g;
        #pragma unroll
        for (int m2 = 0; m2 < 2; m2++) {
            int r0 = rb + m2*16, r1 = r0 + 8;
            #pragma unroll
            for (int ks = 0; ks < 8; ks++) {
                int c = ks*8 + tig;
                qa[m2][ks][0] = Qp[(size_t)r0*DHH + c    ];
                qa[m2][ks][1] = Qp[(size_t)r1*DHH + c    ];
                qa[m2][ks][2] = Qp[(size_t)r0*DHH + c + 4];
                qa[m2][ks][3] = Qp[(size_t)r1*DHH + c + 4];
            }
        }
    }

    auto prefetch = [&](int k0, int st) {
        unsigned* Ks = smem + st * A_STAGE;
        unsigned* Vs = Ks + A_KSTAGE;
        #pragma unroll
        for (int i = 0; i < 8; i++) {
            int idx = tid + i*128;
            int r = idx >> 4, c = (idx & 15) << 2;
            cpa16(&Ks[r*KSTRIDE + c], &Kp[(size_t)(k0 + r)*DHH + c]);
        }
        #pragma unroll
        for (int i = 0; i < 8; i++) {
            int idx = tid + i*128;
            int r = idx >> 4, c = (idx & 15) << 2;
            cpa16(&Vs[r*VSTRIDE + c], &Vp[(size_t)(k0 + r)*DHH + c]);
        }
        if (tid < 16)
            cpa16(&Ks[MSK_OFF + tid*4], &mrow[k0 + tid*4]);
    };

    float o[2][8][4] = {};
    float mx[2][2]   = {{-1e30f,-1e30f},{-1e30f,-1e30f}};
    float lsum[2][2] = {{0.f,0.f},{0.f,0.f}};

    const int src_lo = (lane & ~3) + (tig >> 1);
    const int src_hi = src_lo + 2;
    const bool odd   = (tig & 1);

    prefetch(0, 0);
    cp_commit();

    for (int kt = 0; kt < TT/64; kt++) {
        const int k0  = kt * 64;
        const int buf = kt & 1;

        if (kt + 1 < TT/64) {
            prefetch(k0 + 64, buf ^ 1);
            cp_commit();
            cp_wait1();
        } else {
            cp_wait0();
        }
        __syncthreads();

        const unsigned* Ks = smem + buf * A_STAGE;
        const unsigned* Vs = Ks + A_KSTAGE;
        const float*   msk = reinterpret_cast<const float*>(Ks + MSK_OFF);

        // S = Q K^T
        float s[2][8][4] = {};
        #pragma unroll
        for (int ks = 0; ks < 8; ks++) {
            #pragma unroll
            for (int nf = 0; nf < 8; nf++) {
                unsigned b0 = Ks[(nf*8 + g)*KSTRIDE + ks*8 + tig    ];
                unsigned b1 = Ks[(nf*8 + g)*KSTRIDE + ks*8 + tig + 4];
                mma_tf32(s[0][nf], qa[0][ks][0], qa[0][ks][1], qa[0][ks][2], qa[0][ks][3], b0, b1);
                mma_tf32(s[1][nf], qa[1][ks][0], qa[1][ks][1], qa[1][ks][2], qa[1][ks][3], b0, b1);
            }
        }

        // scale + additive mask + optional causal
        #pragma unroll
        for (int nf = 0; nf < 8; nf++) {
            int cl = nf*8 + tig*2;
            float mk0 = msk[cl], mk1 = msk[cl+1];
            #pragma unroll
            for (int m2 = 0; m2 < 2; m2++) {
                s[m2][nf][0] = s[m2][nf][0]*0.125f + mk0;
                s[m2][nf][1] = s[m2][nf][1]*0.125f + mk1;
                s[m2][nf][2] = s[m2][nf][2]*0.125f + mk0;
                s[m2][nf][3] = s[m2][nf][3]*0.125f + mk1;
                if (mf) {
                    int r0g = q0 + w*32 + m2*16 + g;
                    int r1g = r0g + 8;
                    int c0g = k0 + cl, c1g = c0g + 1;
                    if (c0g >= r0g) s[m2][nf][0] = -1e30f;
                    if (c1g >= r0g) s[m2][nf][1] = -1e30f;
                    if (c0g >= r1g) s[m2][nf][2] = -1e30f;
                    if (c1g >= r1g) s[m2][nf][3] = -1e30f;
                }
            }
        }

        // online softmax, two row-halves per m-frag
        #pragma unroll
        for (int m2 = 0; m2 < 2; m2++) {
            float rm0 = -1e30f, rm1 = -1e30f;
            #pragma unroll
            for (int nf = 0; nf < 8; nf++) {
                rm0 = fmaxf(rm0, fmaxf(s[m2][nf][0], s[m2][nf][1]));
                rm1 = fmaxf(rm1, fmaxf(s[m2][nf][2], s[m2][nf][3]));
            }
            rm0 = fmaxf(rm0, __shfl_xor_sync(0xffffffffu, rm0, 1));
            rm0 = fmaxf(rm0, __shfl_xor_sync(0xffffffffu, rm0, 2));
            rm1 = fmaxf(rm1, __shfl_xor_sync(0xffffffffu, rm1, 1));
            rm1 = fmaxf(rm1, __shfl_xor_sync(0xffffffffu, rm1, 2));

            float mn0 = fmaxf(mx[m2][0], rm0);
            float mn1 = fmaxf(mx[m2][1], rm1);
            float al0 = __expf(mx[m2][0] - mn0);
            float al1 = __expf(mx[m2][1] - mn1);
            mx[m2][0] = mn0; mx[m2][1] = mn1;

            float rs0 = 0.f, rs1 = 0.f;
            #pragma unroll
            for (int nf = 0; nf < 8; nf++) {
                s[m2][nf][0] = __expf(s[m2][nf][0] - mn0);
                s[m2][nf][1] = __expf(s[m2][nf][1] - mn0);
                s[m2][nf][2] = __expf(s[m2][nf][2] - mn1);
                s[m2][nf][3] = __expf(s[m2][nf][3] - mn1);
                rs0 += s[m2][nf][0] + s[m2][nf][1];
                rs1 += s[m2][nf][2] + s[m2][nf][3];
            }
            rs0 += __shfl_xor_sync(0xffffffffu, rs0, 1);
            rs0 += __shfl_xor_sync(0xffffffffu, rs0, 2);
            rs1 += __shfl_xor_sync(0xffffffffu, rs1, 1);
            rs1 += __shfl_xor_sync(0xffffffffu, rs1, 2);
            lsum[m2][0] = lsum[m2][0]*al0 + rs0;
            lsum[m2][1] = lsum[m2][1]*al1 + rs1;

            #pragma unroll
            for (int nf = 0; nf < 8; nf++) {
                o[m2][nf][0] *= al0; o[m2][nf][1] *= al0;
                o[m2][nf][2] *= al1; o[m2][nf][3] *= al1;
            }
        }

        // convert P from C-layout (cols 2tig,2tig+1) to A-layout (cols tig,tig+4)
        // via intra-group shuffles; tf32-round first.  Stored back into s.
        #pragma unroll
        for (int m2 = 0; m2 < 2; m2++) {
            #pragma unroll
            for (int nf = 0; nf < 8; nf++) {
                unsigned u0 = f2tf(s[m2][nf][0]);
                unsigned u1 = f2tf(s[m2][nf][1]);
                unsigned u2 = f2tf(s[m2][nf][2]);
                unsigned u3 = f2tf(s[m2][nf][3]);
                unsigned v0l = __shfl_sync(0xffffffffu, u0, src_lo);
                unsigned v1l = __shfl_sync(0xffffffffu, u1, src_lo);
                unsigned v0h = __shfl_sync(0xffffffffu, u0, src_hi);
                unsigned v1h = __shfl_sync(0xffffffffu, u1, src_hi);
                unsigned v2l = __shfl_sync(0xffffffffu, u2, src_lo);
                unsigned v3l = __shfl_sync(0xffffffffu, u3, src_lo);
                unsigned v2h = __shfl_sync(0xffffffffu, u2, src_hi);
                unsigned v3h = __shfl_sync(0xffffffffu, u3, src_hi);
                s[m2][nf][0] = __uint_as_float(odd ? v1l : v0l);  // a0: row g,   col tig
                s[m2][nf][1] = __uint_as_float(odd ? v3l : v2l);  // a1: row g+8, col tig
                s[m2][nf][2] = __uint_as_float(odd ? v1h : v0h);  // a2: row g,   col tig+4
                s[m2][nf][3] = __uint_as_float(odd ? v3h : v2h);  // a3: row g+8, col tig+4
            }
        }

        // O += P V
        #pragma unroll
        for (int ks = 0; ks < 8; ks++) {
            #pragma unroll
            for (int nf = 0; nf < 8; nf++) {
                unsigned b0 = Vs[(ks*8 + tig    )*VSTRIDE + nf*8 + g];
                unsigned b1 = Vs[(ks*8 + tig + 4)*VSTRIDE + nf*8 + g];
                mma_tf32(o[0][nf],
                    __float_as_uint(s[0][ks][0]), __float_as_uint(s[0][ks][1]),
                    __float_as_uint(s[0][ks][2]), __float_as_uint(s[0][ks][3]), b0, b1);
                mma_tf32(o[1][nf],
                    __float_as_uint(s[1][ks][0]), __float_as_uint(s[1][ks][1]),
                    __float_as_uint(s[1][ks][2]), __float_as_uint(s[1][ks][3]), b0, b1);
            }
        }
        __syncthreads();
    }

    // epilogue: normalize and write [B,T,D]
    #pragma unroll
    for (int m2 = 0; m2 < 2; m2++) {
        int r0g = q0 + w*32 + m2*16 + g;
        int r1g = r0g + 8;
        float inv0 = 1.0f / lsum[m2][0];
        float inv1 = 1.0f / lsum[m2][1];
        #pragma unroll
        for (int nf = 0; nf < 8; nf++) {
            int col = h*64 + nf*8 + tig*2;
            float2 v0 = { o[m2][nf][0]*inv0, o[m2][nf][1]*inv0 };
            float2 v1 = { o[m2][nf][2]*inv1, o[m2][nf][3]*inv1 };
            *reinterpret_cast<float2*>(&out[((size_t)b*TT + r0g)*DDIM + col]) = v0;
            *reinterpret_cast<float2*>(&out[((size_t)b*TT + r1g)*DDIM + col]) = v1;
        }
    }
}

// ---------------------------------------------------------------------------
extern "C" void kernel_launch(void* const* d_in, const int* in_sizes, int n_in,
                              void* d_out, int out_size)
{
    const float* q     = (const float*)d_in[0];
    const float* k     = (const float*)d_in[1];
    const float* amask = (const float*)d_in[2];
    const float* Wq    = (const float*)d_in[3];
    const float* bq    = (const float*)d_in[4];
    const float* Wk    = (const float*)d_in[5];
    const float* bk    = (const float*)d_in[6];
    const float* Wv    = (const float*)d_in[7];
    const float* bv    = (const float*)d_in[8];
    const int*   mf    = (const int*)  d_in[9];
    float* out = (float*)d_out;

    cudaFuncSetAttribute(proj_kernel, cudaFuncAttributeMaxDynamicSharedMemorySize, P_SMEM_BYTES);
    cudaFuncSetAttribute(attn_kernel, cudaFuncAttributeMaxDynamicSharedMemorySize, A_SMEM_BYTES);

    dim3 gp(DDIM/128, MTOT/128, 3);   // (8, 32, 3)
    proj_kernel<<<gp, 256, P_SMEM_BYTES>>>(q, k, Wq, bq, Wk, bk, Wv, bv);

    dim3 ga(TT/128, HH, BB);          // (16, 16, 2)
    attn_kernel<<<ga, 128, A_SMEM_BYTES>>>(amask, mf, out);
}